// round 2
// baseline (speedup 1.0000x reference)
#include <cuda_runtime.h>
#include <math.h>

constexpr int B_  = 32;
constexpr int TD  = 64;
constexpr int TE  = 256;
constexpr int H_  = 512;
constexpr int E_  = 512;
constexpr int V_  = 32000;
constexpr int L_  = 2;
constexpr int NH  = 8;
constexpr int DH  = 64;
constexpr int BTV = B_ * TD * V_;   // 65,536,000
constexpr int LBH = L_ * B_ * H_;   // 32,768

// ---------------- scratch (device globals; no allocation allowed) ----------
__device__ __align__(16) float g_Kh  [B_ * TE * H_];       // (b,s,h,d) natural
__device__ __align__(16) float g_Kh2 [B_ * NH * DH * TE];  // (b,h,d,s) transposed
__device__ __align__(16) float g_Vh  [B_ * TE * H_];       // (b,s,h,d)
__device__ __align__(16) float g_eseq [TD * B_ * E_];      // row r = t*B + b
__device__ __align__(16) float g_eproj[TD * B_ * H_];      // e @ W_in[512:]
__device__ __align__(16) float g_Wcomb[H_ * H_];           // W_o @ W_in[:512]
__device__ __align__(16) float g_hA[LBH];
__device__ __align__(16) float g_hB[LBH];
__device__ __align__(16) float g_ctx[B_ * H_];
__device__ __align__(16) float g_xra[B_ * H_];
__device__ __align__(16) float g_xrb[B_ * H_];
__device__ __align__(16) float g_ys [TD * B_ * H_];        // row r = t*B + b

// ---------------- generic fp32 SIMT GEMM: 128x128x8 tile, 256 thr, 8x8/thr --
// C[M,N] = A[M,K](lda) @ B[K,N](ldb) (+bias[n]); mode 0: row-major C (ldc=N)
// mode 1: logits remap: row m -> (t=m/32, b=m%32) -> out[b*TD*V + t*V + n]
__global__ __launch_bounds__(256) void sgemm_kernel(
    int M, int N, int K,
    const float* __restrict__ A, int lda,
    const float* __restrict__ B, int ldb,
    float* __restrict__ C,
    const float* __restrict__ bias, int mode)
{
    __shared__ float As[8][132];
    __shared__ float Bs[8][132];
    const int tid = threadIdx.x;
    const int bx = blockIdx.x, by = blockIdx.y;

    const float* Aptr = A + (size_t)(by * 128 + (tid >> 1)) * lda + (tid & 1) * 4;
    const float* Bptr = B + (size_t)(tid >> 5) * ldb + bx * 128 + (tid & 31) * 4;

    const int ty = tid >> 4, tx = tid & 15;
    float acc[8][8];
#pragma unroll
    for (int i = 0; i < 8; i++)
#pragma unroll
        for (int j = 0; j < 8; j++) acc[i][j] = 0.f;

    for (int k0 = 0; k0 < K; k0 += 8) {
        float4 av = *(const float4*)(Aptr + k0);
        float4 bv = *(const float4*)(Bptr + (size_t)k0 * ldb);
        __syncthreads();
        const int ar_ = tid >> 1, ac_ = (tid & 1) * 4;
        As[ac_ + 0][ar_] = av.x;
        As[ac_ + 1][ar_] = av.y;
        As[ac_ + 2][ar_] = av.z;
        As[ac_ + 3][ar_] = av.w;
        *(float4*)&Bs[tid >> 5][(tid & 31) * 4] = bv;
        __syncthreads();
#pragma unroll
        for (int kk = 0; kk < 8; kk++) {
            float ar[8], br[8];
            *(float4*)(ar)     = *(float4*)&As[kk][ty * 4];
            *(float4*)(ar + 4) = *(float4*)&As[kk][ty * 4 + 64];
            *(float4*)(br)     = *(float4*)&Bs[kk][tx * 4];
            *(float4*)(br + 4) = *(float4*)&Bs[kk][tx * 4 + 64];
#pragma unroll
            for (int i = 0; i < 8; i++)
#pragma unroll
                for (int j = 0; j < 8; j++) acc[i][j] += ar[i] * br[j];
        }
    }

#pragma unroll
    for (int i = 0; i < 8; i++) {
        int m = by * 128 + ty * 4 + (i & 3) + (i >> 2) * 64;
#pragma unroll
        for (int j = 0; j < 8; j++) {
            int n = bx * 128 + tx * 4 + (j & 3) + (j >> 2) * 64;
            float v = acc[i][j] + (bias ? bias[n] : 0.f);
            if (mode == 0) {
                C[(size_t)m * N + n] = v;
            } else {
                int tt = m >> 5, bb = m & 31;
                C[(size_t)bb * (TD * V_) + (size_t)tt * V_ + n] = v;
            }
        }
    }
}

// ---------------- transpose Kh (b,s,h,d) -> Kh2 (b,h,d,s) -------------------
__global__ void transpose_k_kernel()
{
    __shared__ float t[32][33];
    int bh = blockIdx.x;                 // b*8 + h
    int b = bh >> 3, h = bh & 7;
    int s0 = blockIdx.y * 32, d0 = blockIdx.z * 32;
    for (int yy = threadIdx.y; yy < 32; yy += 8)
        t[yy][threadIdx.x] = g_Kh[((size_t)(b * 256 + s0 + yy) * 8 + h) * 64 + d0 + threadIdx.x];
    __syncthreads();
    for (int yy = threadIdx.y; yy < 32; yy += 8)
        g_Kh2[((size_t)(bh) * 64 + d0 + yy) * 256 + s0 + threadIdx.x] = t[threadIdx.x][yy];
}

// ---------------- embedding gather: eseq[t*B+b][:] = emb[x[b][t]][:] --------
__global__ void gather_emb_kernel(const int* __restrict__ x, const float* __restrict__ emb)
{
    int r = blockIdx.x;            // t*B + b
    int t = r >> 5, b = r & 31;
    int tok = x[b * TD + t];
    const float4* src = (const float4*)(emb + (size_t)tok * E_);
    float4* dst = (float4*)(g_eseq + (size_t)r * E_);
    for (int i = threadIdx.x; i < E_ / 4; i += blockDim.x) dst[i] = src[i];
}

// ---------------- generic copy ---------------------------------------------
__global__ void copy_kernel(const float* __restrict__ src, float* __restrict__ dst, int n)
{
    int i = blockIdx.x * blockDim.x + threadIdx.x;
    if (i < n) dst[i] = src[i];
}

// ---------------- per-step attention (q proj + scores + softmax + ctx) -----
__global__ __launch_bounds__(256) void attn_kernel(
    const float* __restrict__ hlast,   // [B,H] (layer L-1 slice of h_in)
    const float* __restrict__ Wq,      // [H,H]
    const int*   __restrict__ valid)
{
    int bh = blockIdx.x;               // b*8 + h
    int b = bh >> 3, h = bh & 7;
    int tid = threadIdx.x;
    __shared__ float sh[512];
    __shared__ float sq[64];
    __shared__ float sp[256];
    __shared__ float red[256];

    sh[tid]       = hlast[b * 512 + tid];
    sh[tid + 256] = hlast[b * 512 + tid + 256];
    __syncthreads();

    int d = tid & 63, c = tid >> 6;
    {   // q[d] = sum_k h[k] * Wq[k][h*64+d]
        float acc = 0.f;
        const float* wq = Wq + h * 64 + d;
        for (int k = c * 128; k < c * 128 + 128; k++) acc += sh[k] * wq[(size_t)k * 512];
        red[tid] = acc;
    }
    __syncthreads();
    if (tid < 64) sq[tid] = red[tid] + red[tid + 64] + red[tid + 128] + red[tid + 192];
    __syncthreads();

    // scores (thread = key position s)
    float sc = -1e6f;
    int vl = valid[b];
    if (tid < vl) {
        float a = 0.f;
        const float* kp = g_Kh2 + (size_t)bh * 64 * 256 + tid;
#pragma unroll 8
        for (int dd = 0; dd < 64; dd++) a += sq[dd] * kp[dd * 256];
        sc = a * 0.125f;
    }
    // softmax over 256
    red[tid] = sc; __syncthreads();
    for (int off = 128; off > 0; off >>= 1) {
        if (tid < off) red[tid] = fmaxf(red[tid], red[tid + off]);
        __syncthreads();
    }
    float mx = red[0];
    __syncthreads();
    float p = expf(sc - mx);
    red[tid] = p; __syncthreads();
    for (int off = 128; off > 0; off >>= 1) {
        if (tid < off) red[tid] += red[tid + off];
        __syncthreads();
    }
    float sum = red[0];
    sp[tid] = p / sum;
    __syncthreads();

    // ctx[d] = sum_s attn[s] * Vh[b][s][h][d]
    {
        float a = 0.f;
        const float* vp = g_Vh + ((size_t)(b * 256 + c * 64) * 8 + h) * 64 + d;
        for (int ss = 0; ss < 64; ss++) a += sp[c * 64 + ss] * vp[(size_t)ss * 512];
        red[tid] = a;
    }
    __syncthreads();
    if (tid < 64)
        g_ctx[b * 512 + h * 64 + tid] =
            red[tid] + red[tid + 64] + red[tid + 128] + red[tid + 192];
}

// ---------------- xr = ctx @ Wcomb + eproj[t] -------------------------------
__global__ __launch_bounds__(256) void xr_kernel(const float* __restrict__ eproj_t)
{
    int b0 = blockIdx.x * 4;           // 8 b-tiles
    int j0 = blockIdx.y * 128;         // 4 j-tiles
    int tid = threadIdx.x;
    __shared__ float sc[4][512];
    for (int i = tid; i < 4 * 512; i += 256) sc[i >> 9][i & 511] = g_ctx[b0 * 512 + i];
    __syncthreads();
    int j = tid & 127;
    int bo = (tid >> 7) * 2;           // {0,2}
    float a0 = eproj_t[(b0 + bo + 0) * 512 + j0 + j];
    float a1 = eproj_t[(b0 + bo + 1) * 512 + j0 + j];
    const float* w = g_Wcomb + j0 + j;
    for (int k = 0; k < 512; k++) {
        float wv = w[(size_t)k * 512];
        a0 += sc[bo + 0][k] * wv;
        a1 += sc[bo + 1][k] * wv;
    }
    g_xra[(b0 + bo + 0) * 512 + j0 + j] = a0;
    g_xra[(b0 + bo + 1) * 512 + j0 + j] = a1;
}

// ---------------- fused LayerNorm + GRU cell + alpha residual ---------------
__global__ __launch_bounds__(256) void gru_kernel(
    const float* __restrict__ xr_in,
    const float* __restrict__ h_in,    // layer slice [B,H]
    float* __restrict__ h_out,         // layer slice [B,H]
    float* __restrict__ xr_out,        // xr buffer or ys[t]
    const float* __restrict__ Wih,     // [3H,H] layer slice
    const float* __restrict__ Whh,
    const float* __restrict__ bih,     // [3H]
    const float* __restrict__ bhh,
    const float* __restrict__ gamma,   // [H] layer slice
    const float* __restrict__ beta,
    const float* __restrict__ alpha_p)
{
    int b0 = blockIdx.x * 4;           // 8 b-tiles
    int j0 = blockIdx.y * 32;          // 16 j-tiles
    int tid = threadIdx.x, lane = tid & 31, w = tid >> 5;
    __shared__ float sxin[4][512];
    __shared__ float shh [4][512];
    __shared__ float s_mu[4], s_rs[4];

    for (int i = tid; i < 2048; i += 256) sxin[i >> 9][i & 511] = xr_in[b0 * 512 + i];
    for (int i = tid; i < 2048; i += 256) shh [i >> 9][i & 511] = h_in [b0 * 512 + i];
    __syncthreads();

    if (w < 4) {  // per-row LN stats
        float s1 = 0.f, s2 = 0.f;
        for (int k = lane; k < 512; k += 32) {
            float v = sxin[w][k];
            s1 += v; s2 += v * v;
        }
        for (int o = 16; o; o >>= 1) {
            s1 += __shfl_xor_sync(0xffffffffu, s1, o);
            s2 += __shfl_xor_sync(0xffffffffu, s2, o);
        }
        if (lane == 0) {
            float mu = s1 * (1.f / 512.f);
            float var = s2 * (1.f / 512.f) - mu * mu;
            s_mu[w] = mu;
            s_rs[w] = rsqrtf(var + 1e-5f);
        }
    }
    __syncthreads();
    for (int i = tid; i < 2048; i += 256) {
        int bb = i >> 9, k = i & 511;
        sxin[bb][k] = (sxin[bb][k] - s_mu[bb]) * s_rs[bb] * gamma[k] + beta[k];
    }
    __syncthreads();

    float alpha = *alpha_p;
    // warp w handles j = j0 + w*4 + (i>>2), b = i&3 (16 pairs/warp)
#pragma unroll 1
    for (int i = 0; i < 16; i++) {
        int bb = i & 3;
        int jg = j0 + w * 4 + (i >> 2);
        const float* wr = Wih + (size_t)jg * 512;
        const float* wz = Wih + (size_t)(jg + 512) * 512;
        const float* wg = Wih + (size_t)(jg + 1024) * 512;
        const float* ur = Whh + (size_t)jg * 512;
        const float* uz = Whh + (size_t)(jg + 512) * 512;
        const float* ug = Whh + (size_t)(jg + 1024) * 512;
        float ir = 0.f, iz = 0.f, ig = 0.f, hr = 0.f, hz = 0.f, hg = 0.f;
        for (int k = lane; k < 512; k += 32) {
            float xv = sxin[bb][k], hv = shh[bb][k];
            ir += xv * wr[k]; iz += xv * wz[k]; ig += xv * wg[k];
            hr += hv * ur[k]; hz += hv * uz[k]; hg += hv * ug[k];
        }
        for (int o = 16; o; o >>= 1) {
            ir += __shfl_xor_sync(0xffffffffu, ir, o);
            iz += __shfl_xor_sync(0xffffffffu, iz, o);
            ig += __shfl_xor_sync(0xffffffffu, ig, o);
            hr += __shfl_xor_sync(0xffffffffu, hr, o);
            hz += __shfl_xor_sync(0xffffffffu, hz, o);
            hg += __shfl_xor_sync(0xffffffffu, hg, o);
        }
        if (lane == 0) {
            ir += bih[jg];        hr += bhh[jg];
            iz += bih[jg + 512];  hz += bhh[jg + 512];
            ig += bih[jg + 1024]; hg += bhh[jg + 1024];
            float r = 1.f / (1.f + expf(-(ir + hr)));
            float z = 1.f / (1.f + expf(-(iz + hz)));
            float g = tanhf(ig + r * hg);
            float hprev = shh[bb][jg];
            float hn = (1.f - z) * g + z * hprev;
            h_out [(b0 + bb) * 512 + jg] = hn;
            xr_out[(b0 + bb) * 512 + jg] = xr_in[(b0 + bb) * 512 + jg] + alpha * hn;
        }
    }
}

// ============================ host orchestration ============================
extern "C" void kernel_launch(void* const* d_in, const int* in_sizes, int n_in,
                              void* d_out, int out_size)
{
    const int*   x    = (const int*)  d_in[0];
    const float* enc  = (const float*)d_in[1];
    const float* h0   = (const float*)d_in[2];
    const int*   vlen = (const int*)  d_in[3];
    const float* emb  = (const float*)d_in[4];
    const float* Wq   = (const float*)d_in[5];
    const float* Wk   = (const float*)d_in[6];
    const float* Wv   = (const float*)d_in[7];
    const float* Wo   = (const float*)d_in[8];
    const float* Win  = (const float*)d_in[9];
    const float* lng  = (const float*)d_in[10];
    const float* lnb  = (const float*)d_in[11];
    const float* alph = (const float*)d_in[12];
    const float* Wih  = (const float*)d_in[13];
    const float* Whh  = (const float*)d_in[14];
    const float* bih  = (const float*)d_in[15];
    const float* bhh  = (const float*)d_in[16];
    const float* Wd   = (const float*)d_in[17];
    const float* bd   = (const float*)d_in[18];
    float* out = (float*)d_out;

    float *pKh, *pVh, *pEseq, *pEproj, *pWcomb, *pHA, *pHB, *pXra, *pXrb, *pYs;
    cudaGetSymbolAddress((void**)&pKh,    g_Kh);
    cudaGetSymbolAddress((void**)&pVh,    g_Vh);
    cudaGetSymbolAddress((void**)&pEseq,  g_eseq);
    cudaGetSymbolAddress((void**)&pEproj, g_eproj);
    cudaGetSymbolAddress((void**)&pWcomb, g_Wcomb);
    cudaGetSymbolAddress((void**)&pHA,    g_hA);
    cudaGetSymbolAddress((void**)&pHB,    g_hB);
    cudaGetSymbolAddress((void**)&pXra,   g_xra);
    cudaGetSymbolAddress((void**)&pXrb,   g_xrb);
    cudaGetSymbolAddress((void**)&pYs,    g_ys);

    // h init
    copy_kernel<<<(LBH + 255) / 256, 256>>>(h0, pHA, LBH);

    // K/V projections: (B*TE, 2H) @ (2H, H)
    sgemm_kernel<<<dim3(H_ / 128, (B_ * TE) / 128), 256>>>(
        B_ * TE, H_, 2 * H_, enc, 2 * H_, Wk, H_, pKh, nullptr, 0);
    sgemm_kernel<<<dim3(H_ / 128, (B_ * TE) / 128), 256>>>(
        B_ * TE, H_, 2 * H_, enc, 2 * H_, Wv, H_, pVh, nullptr, 0);
    transpose_k_kernel<<<dim3(B_ * NH, TE / 32, DH / 32), dim3(32, 8)>>>();

    // embedding gather + e @ W_in[512:]
    gather_emb_kernel<<<TD * B_, 128>>>(x, emb);
    sgemm_kernel<<<dim3(H_ / 128, (TD * B_) / 128), 256>>>(
        TD * B_, H_, E_, pEseq, E_, Win + 512 * H_, H_, pEproj, nullptr, 0);

    // W_comb = W_o @ W_in[:512]
    sgemm_kernel<<<dim3(H_ / 128, H_ / 128), 256>>>(
        H_, H_, H_, Wo, H_, Win, H_, pWcomb, nullptr, 0);

    // sequential decode scan
    for (int t = 0; t < TD; t++) {
        const float* hin = (t & 1) ? pHB : pHA;
        float*       hout = (t & 1) ? pHA : pHB;

        attn_kernel<<<B_ * NH, 256>>>(hin + (L_ - 1) * B_ * H_, Wq, vlen);
        xr_kernel<<<dim3(8, 4), 256>>>(pEproj + (size_t)t * B_ * H_);
        gru_kernel<<<dim3(8, 16), 256>>>(
            pXra, hin, hout, pXrb,
            Wih, Whh, bih, bhh, lng, lnb, alph + 0);
        gru_kernel<<<dim3(8, 16), 256>>>(
            pXrb, hin + B_ * H_, hout + B_ * H_, pYs + (size_t)t * B_ * H_,
            Wih + 3 * H_ * H_, Whh + 3 * H_ * H_, bih + 3 * H_, bhh + 3 * H_,
            lng + H_, lnb + H_, alph + 1);
    }

    // logits = ys @ W_dense + b_dense, written transposed to (B, T, V)
    sgemm_kernel<<<dim3(V_ / 128, (TD * B_) / 128), 256>>>(
        TD * B_, V_, H_, pYs, H_, Wd, V_, out, bd, 1);

    // final hidden state (t=63 odd -> final state lives in g_hA)
    if (out_size >= BTV + LBH)
        copy_kernel<<<(LBH + 255) / 256, 256>>>(pHA, out + BTV, LBH);
}

// round 4
// speedup vs baseline: 1.0706x; 1.0706x over previous
#include <cuda_runtime.h>
#include <cuda_bf16.h>
#include <math.h>
#include <stdint.h>

constexpr int B_  = 32;
constexpr int TD  = 64;
constexpr int TE  = 256;
constexpr int H_  = 512;
constexpr int E_  = 512;
constexpr int V_  = 32000;
constexpr int L_  = 2;
constexpr int NH  = 8;
constexpr int DH  = 64;
constexpr int BTV = B_ * TD * V_;   // 65,536,000
constexpr int LBH = L_ * B_ * H_;   // 32,768

// ---------------- scratch (device globals; no allocation allowed) ----------
__device__ __align__(16) float g_Kh  [B_ * TE * H_];       // (b,s,h,d)
__device__ __align__(16) float g_Kh2 [B_ * NH * DH * TE];  // (b,h,d,s)
__device__ __align__(16) float g_Vh  [B_ * TE * H_];
__device__ __align__(16) float g_eproj[TD * B_ * H_];
__device__ __align__(16) float g_Wcomb[H_ * H_];
__device__ __align__(16) float g_hA[LBH];
__device__ __align__(16) float g_hB[LBH];
__device__ __align__(16) float g_ctx[B_ * H_];
__device__ __align__(16) float g_xra[B_ * H_];
__device__ __align__(16) float g_xrb[B_ * H_];
__device__ __align__(16) float g_ys [TD * B_ * H_];

// bf16 hi/lo split buffers for tensor-core GEMMs
__device__ __align__(16) __nv_bfloat16 g_enc_h [B_ * TE * 2 * H_];
__device__ __align__(16) __nv_bfloat16 g_enc_l [B_ * TE * 2 * H_];
__device__ __align__(16) __nv_bfloat16 g_Wkt_h [H_ * 2 * H_];     // [N=512][K=1024]
__device__ __align__(16) __nv_bfloat16 g_Wkt_l [H_ * 2 * H_];
__device__ __align__(16) __nv_bfloat16 g_Wvt_h [H_ * 2 * H_];
__device__ __align__(16) __nv_bfloat16 g_Wvt_l [H_ * 2 * H_];
__device__ __align__(16) __nv_bfloat16 g_Wint_h[H_ * H_];          // [512][512]
__device__ __align__(16) __nv_bfloat16 g_Wint_l[H_ * H_];
__device__ __align__(16) __nv_bfloat16 g_Wdt_h [V_ * H_];          // [32000][512]
__device__ __align__(16) __nv_bfloat16 g_Wdt_l [V_ * H_];
__device__ __align__(16) __nv_bfloat16 g_eseq_h[TD * B_ * E_];
__device__ __align__(16) __nv_bfloat16 g_eseq_l[TD * B_ * E_];
__device__ __align__(16) __nv_bfloat16 g_ys_h  [TD * B_ * H_];
__device__ __align__(16) __nv_bfloat16 g_ys_l  [TD * B_ * H_];

// ======================= mma.sync helpers (compute_103-safe) ================
__device__ __forceinline__ uint32_t smem_u32(const void* p) {
    uint32_t a;
    asm("{ .reg .u64 t; cvta.to.shared.u64 t, %1; cvt.u32.u64 %0, t; }"
        : "=r"(a) : "l"(p));
    return a;
}
__device__ __forceinline__ void ldsm4(uint32_t (&r)[4], uint32_t addr) {
    asm volatile("ldmatrix.sync.aligned.m8n8.x4.shared.b16 {%0,%1,%2,%3}, [%4];"
        : "=r"(r[0]), "=r"(r[1]), "=r"(r[2]), "=r"(r[3]) : "r"(addr));
}
__device__ __forceinline__ void mma16816(float (&d)[4], const uint32_t (&a)[4],
                                         uint32_t b0, uint32_t b1) {
    asm volatile(
        "mma.sync.aligned.m16n8k16.row.col.f32.bf16.bf16.f32 "
        "{%0,%1,%2,%3}, {%4,%5,%6,%7}, {%8,%9}, {%0,%1,%2,%3};"
        : "+f"(d[0]), "+f"(d[1]), "+f"(d[2]), "+f"(d[3])
        : "r"(a[0]), "r"(a[1]), "r"(a[2]), "r"(a[3]), "r"(b0), "r"(b1));
}

// ============ HMMA compensated-bf16 GEMM: C[M,N] = A[M,K] @ Bt[N,K]^T =======
// A,B given as hi/lo bf16 splits; D = Ah*Bh + Ah*Bl + Al*Bh (fp32 accum).
// Block tile 128x128, BK=32, 8 warps (4m x 2n), warp tile 32x64.
// mode 0: C row-major [M][N]; mode 1: logits remap row m->(t,b)
constexpr int BKg  = 32;
constexpr int LDSg = BKg + 8;   // 40 bf16 per row (+16B pad, conflict-free LDSM)

__global__ __launch_bounds__(256) void mma_gemm_kernel(
    int M, int N, int K,
    const __nv_bfloat16* __restrict__ Ah, const __nv_bfloat16* __restrict__ Al,
    const __nv_bfloat16* __restrict__ Bh, const __nv_bfloat16* __restrict__ Bl,
    float* __restrict__ C, const float* __restrict__ bias, int mode)
{
    __shared__ __nv_bfloat16 sAh[128 * LDSg], sAl[128 * LDSg];
    __shared__ __nv_bfloat16 sBh[128 * LDSg], sBl[128 * LDSg];

    const int tid = threadIdx.x, lane = tid & 31, wid = tid >> 5;
    const int wm = wid >> 1, wn = wid & 1;
    const int n0 = blockIdx.x * 128, m0 = blockIdx.y * 128;

    float acc[2][8][4];
#pragma unroll
    for (int i = 0; i < 2; i++)
#pragma unroll
        for (int j = 0; j < 8; j++)
#pragma unroll
            for (int k = 0; k < 4; k++) acc[i][j][k] = 0.f;

    const int lrow = tid >> 2;            // 0..63
    const int lcol = (tid & 3) * 8;       // 0,8,16,24

    for (int kb = 0; kb < K; kb += BKg) {
        __syncthreads();
#pragma unroll
        for (int h = 0; h < 2; h++) {
            int row = lrow + h * 64;
            size_t ga = (size_t)(m0 + row) * K + kb + lcol;
            size_t gb = (size_t)(n0 + row) * K + kb + lcol;
            uint32_t so = row * LDSg + lcol;
            *(uint4*)&sAh[so] = *(const uint4*)(Ah + ga);
            *(uint4*)&sAl[so] = *(const uint4*)(Al + ga);
            *(uint4*)&sBh[so] = *(const uint4*)(Bh + gb);
            *(uint4*)&sBl[so] = *(const uint4*)(Bl + gb);
        }
        __syncthreads();

#pragma unroll
        for (int ks = 0; ks < BKg; ks += 16) {
            uint32_t ah[2][4], al[2][4];
            const uint32_t fcol = ks + (lane >> 4) * 8;
#pragma unroll
            for (int mi = 0; mi < 2; mi++) {
                uint32_t arow = wm * 32 + mi * 16 + (lane & 15);
                ldsm4(ah[mi], smem_u32(&sAh[arow * LDSg + fcol]));
                ldsm4(al[mi], smem_u32(&sAl[arow * LDSg + fcol]));
            }
#pragma unroll
            for (int nj = 0; nj < 4; nj++) {
                uint32_t brow = wn * 64 + nj * 16 + (lane & 15);
                uint32_t bh[4], bl[4];
                ldsm4(bh, smem_u32(&sBh[brow * LDSg + fcol]));
                ldsm4(bl, smem_u32(&sBl[brow * LDSg + fcol]));
#pragma unroll
                for (int mi = 0; mi < 2; mi++) {
                    mma16816(acc[mi][2 * nj],     ah[mi], bh[0], bh[2]);
                    mma16816(acc[mi][2 * nj + 1], ah[mi], bh[1], bh[3]);
                    mma16816(acc[mi][2 * nj],     ah[mi], bl[0], bl[2]);
                    mma16816(acc[mi][2 * nj + 1], ah[mi], bl[1], bl[3]);
                    mma16816(acc[mi][2 * nj],     al[mi], bh[0], bh[2]);
                    mma16816(acc[mi][2 * nj + 1], al[mi], bh[1], bh[3]);
                }
            }
        }
    }

    // epilogue: direct register -> global (float2 per half-tile)
#pragma unroll
    for (int mi = 0; mi < 2; mi++) {
        int row = m0 + wm * 32 + mi * 16 + (lane >> 2);
#pragma unroll
        for (int nt = 0; nt < 8; nt++) {
            int col = n0 + wn * 64 + nt * 8 + (lane & 3) * 2;
            float bb0 = bias ? bias[col] : 0.f;
            float bb1 = bias ? bias[col + 1] : 0.f;
            float2 v0 = make_float2(acc[mi][nt][0] + bb0, acc[mi][nt][1] + bb1);
            float2 v1 = make_float2(acc[mi][nt][2] + bb0, acc[mi][nt][3] + bb1);
            if (mode == 0) {
                *(float2*)&C[(size_t)row * N + col] = v0;
                *(float2*)&C[(size_t)(row + 8) * N + col] = v1;
            } else {
                int t0 = row >> 5, b0v_ = row & 31;
                int t1 = (row + 8) >> 5, b1v_ = (row + 8) & 31;
                *(float2*)&C[(size_t)b0v_ * (TD * V_) + (size_t)t0 * V_ + col] = v0;
                *(float2*)&C[(size_t)b1v_ * (TD * V_) + (size_t)t1 * V_ + col] = v1;
            }
        }
    }
}

// ---------------- fp32 -> bf16 hi/lo split helpers --------------------------
__device__ __forceinline__ void bsplit(float x, __nv_bfloat16& h, __nv_bfloat16& l) {
    h = __float2bfloat16(x);
    l = __float2bfloat16(x - __bfloat162float(h));
}

__global__ void aconv_kernel(const float* __restrict__ src,
                             __nv_bfloat16* __restrict__ oh,
                             __nv_bfloat16* __restrict__ ol, int n4)
{
    int i = blockIdx.x * blockDim.x + threadIdx.x;
    if (i >= n4) return;
    float4 v = ((const float4*)src)[i];
    __nv_bfloat16 h0, h1, h2, h3, l0, l1, l2, l3;
    bsplit(v.x, h0, l0); bsplit(v.y, h1, l1);
    bsplit(v.z, h2, l2); bsplit(v.w, h3, l3);
    ((__nv_bfloat162*)oh)[2 * i]     = __nv_bfloat162(h0, h1);
    ((__nv_bfloat162*)oh)[2 * i + 1] = __nv_bfloat162(h2, h3);
    ((__nv_bfloat162*)ol)[2 * i]     = __nv_bfloat162(l0, l1);
    ((__nv_bfloat162*)ol)[2 * i + 1] = __nv_bfloat162(l2, l3);
}

// transpose-convert: W[row_off+k][n] (ld N) -> out[n][k] hi/lo, dims K x N
__global__ void tconv_kernel(const float* __restrict__ W, int K, int N, int row_off,
                             __nv_bfloat16* __restrict__ oh, __nv_bfloat16* __restrict__ ol)
{
    __shared__ float t[32][33];
    int n0 = blockIdx.x * 32, k0 = blockIdx.y * 32;
    for (int ky = threadIdx.y; ky < 32; ky += 8)
        t[ky][threadIdx.x] = W[(size_t)(row_off + k0 + ky) * N + n0 + threadIdx.x];
    __syncthreads();
    for (int ny = threadIdx.y; ny < 32; ny += 8) {
        float v = t[threadIdx.x][ny];
        __nv_bfloat16 h, l; bsplit(v, h, l);
        size_t o = (size_t)(n0 + ny) * K + k0 + threadIdx.x;
        oh[o] = h; ol[o] = l;
    }
}

// ---------------- fp32 SIMT GEMM (kept for small Wcomb) ---------------------
__global__ __launch_bounds__(256) void sgemm_kernel(
    int M, int N, int K,
    const float* __restrict__ A, int lda,
    const float* __restrict__ B, int ldb,
    float* __restrict__ C,
    const float* __restrict__ bias, int mode)
{
    __shared__ float As[8][132];
    __shared__ float Bs[8][132];
    const int tid = threadIdx.x;
    const int bx = blockIdx.x, by = blockIdx.y;
    const float* Aptr = A + (size_t)(by * 128 + (tid >> 1)) * lda + (tid & 1) * 4;
    const float* Bptr = B + (size_t)(tid >> 5) * ldb + bx * 128 + (tid & 31) * 4;
    const int ty = tid >> 4, tx = tid & 15;
    float acc[8][8];
#pragma unroll
    for (int i = 0; i < 8; i++)
#pragma unroll
        for (int j = 0; j < 8; j++) acc[i][j] = 0.f;
    for (int k0 = 0; k0 < K; k0 += 8) {
        float4 av = *(const float4*)(Aptr + k0);
        float4 bv = *(const float4*)(Bptr + (size_t)k0 * ldb);
        __syncthreads();
        const int ar_ = tid >> 1, ac_ = (tid & 1) * 4;
        As[ac_ + 0][ar_] = av.x; As[ac_ + 1][ar_] = av.y;
        As[ac_ + 2][ar_] = av.z; As[ac_ + 3][ar_] = av.w;
        *(float4*)&Bs[tid >> 5][(tid & 31) * 4] = bv;
        __syncthreads();
#pragma unroll
        for (int kk = 0; kk < 8; kk++) {
            float ar[8], br[8];
            *(float4*)(ar)     = *(float4*)&As[kk][ty * 4];
            *(float4*)(ar + 4) = *(float4*)&As[kk][ty * 4 + 64];
            *(float4*)(br)     = *(float4*)&Bs[kk][tx * 4];
            *(float4*)(br + 4) = *(float4*)&Bs[kk][tx * 4 + 64];
#pragma unroll
            for (int i = 0; i < 8; i++)
#pragma unroll
                for (int j = 0; j < 8; j++) acc[i][j] += ar[i] * br[j];
        }
    }
#pragma unroll
    for (int i = 0; i < 8; i++) {
        int m = by * 128 + ty * 4 + (i & 3) + (i >> 2) * 64;
#pragma unroll
        for (int j = 0; j < 8; j++) {
            int n = bx * 128 + tx * 4 + (j & 3) + (j >> 2) * 64;
            float v = acc[i][j] + (bias ? bias[n] : 0.f);
            if (mode == 0) C[(size_t)m * N + n] = v;
            else {
                int tt = m >> 5, bb = m & 31;
                C[(size_t)bb * (TD * V_) + (size_t)tt * V_ + n] = v;
            }
        }
    }
}

// ---------------- transpose Kh (b,s,h,d) -> Kh2 (b,h,d,s) -------------------
__global__ void transpose_k_kernel()
{
    __shared__ float t[32][33];
    int bh = blockIdx.x;
    int b = bh >> 3, h = bh & 7;
    int s0 = blockIdx.y * 32, d0 = blockIdx.z * 32;
    for (int yy = threadIdx.y; yy < 32; yy += 8)
        t[yy][threadIdx.x] = g_Kh[((size_t)(b * 256 + s0 + yy) * 8 + h) * 64 + d0 + threadIdx.x];
    __syncthreads();
    for (int yy = threadIdx.y; yy < 32; yy += 8)
        g_Kh2[((size_t)(bh) * 64 + d0 + yy) * 256 + s0 + threadIdx.x] = t[threadIdx.x][yy];
}

// ---------------- embedding gather -> bf16 hi/lo ----------------------------
__global__ void gather_emb_kernel(const int* __restrict__ x, const float* __restrict__ emb)
{
    int r = blockIdx.x;            // t*B + b
    int t = r >> 5, b = r & 31;
    int tok = x[b * TD + t];
    const float* src = emb + (size_t)tok * E_;
    for (int i = threadIdx.x; i < E_; i += blockDim.x) {
        __nv_bfloat16 h, l; bsplit(src[i], h, l);
        g_eseq_h[(size_t)r * E_ + i] = h;
        g_eseq_l[(size_t)r * E_ + i] = l;
    }
}

__global__ void copy_kernel(const float* __restrict__ src, float* __restrict__ dst, int n)
{
    int i = blockIdx.x * blockDim.x + threadIdx.x;
    if (i < n) dst[i] = src[i];
}

// ---------------- per-step attention ----------------------------------------
__global__ __launch_bounds__(256) void attn_kernel(
    const float* __restrict__ hlast,
    const float* __restrict__ Wq,
    const int*   __restrict__ valid)
{
    int bh = blockIdx.x;
    int b = bh >> 3, h = bh & 7;
    int tid = threadIdx.x;
    __shared__ float sh[512];
    __shared__ float sq[64];
    __shared__ float sp[256];
    __shared__ float red[256];

    sh[tid]       = hlast[b * 512 + tid];
    sh[tid + 256] = hlast[b * 512 + tid + 256];
    __syncthreads();

    int d = tid & 63, c = tid >> 6;
    {
        float acc = 0.f;
        const float* wq = Wq + h * 64 + d;
        for (int k = c * 128; k < c * 128 + 128; k++) acc += sh[k] * wq[(size_t)k * 512];
        red[tid] = acc;
    }
    __syncthreads();
    if (tid < 64) sq[tid] = red[tid] + red[tid + 64] + red[tid + 128] + red[tid + 192];
    __syncthreads();

    float sc = -1e6f;
    int vl = valid[b];
    if (tid < vl) {
        float a = 0.f;
        const float* kp = g_Kh2 + (size_t)bh * 64 * 256 + tid;
#pragma unroll 8
        for (int dd = 0; dd < 64; dd++) a += sq[dd] * kp[dd * 256];
        sc = a * 0.125f;
    }
    red[tid] = sc; __syncthreads();
    for (int off = 128; off > 0; off >>= 1) {
        if (tid < off) red[tid] = fmaxf(red[tid], red[tid + off]);
        __syncthreads();
    }
    float mx = red[0];
    __syncthreads();
    float p = expf(sc - mx);
    red[tid] = p; __syncthreads();
    for (int off = 128; off > 0; off >>= 1) {
        if (tid < off) red[tid] += red[tid + off];
        __syncthreads();
    }
    float sum = red[0];
    sp[tid] = p / sum;
    __syncthreads();

    {
        float a = 0.f;
        const float* vp = g_Vh + ((size_t)(b * 256 + c * 64) * 8 + h) * 64 + d;
        for (int ss = 0; ss < 64; ss++) a += sp[c * 64 + ss] * vp[(size_t)ss * 512];
        red[tid] = a;
    }
    __syncthreads();
    if (tid < 64)
        g_ctx[b * 512 + h * 64 + tid] =
            red[tid] + red[tid + 64] + red[tid + 128] + red[tid + 192];
}

// ---------------- xr = ctx @ Wcomb + eproj[t] -------------------------------
__global__ __launch_bounds__(256) void xr_kernel(const float* __restrict__ eproj_t)
{
    int b0 = blockIdx.x * 4;
    int j0 = blockIdx.y * 128;
    int tid = threadIdx.x;
    __shared__ float sc[4][512];
    for (int i = tid; i < 4 * 512; i += 256) sc[i >> 9][i & 511] = g_ctx[b0 * 512 + i];
    __syncthreads();
    int j = tid & 127;
    int bo = (tid >> 7) * 2;
    float a0 = eproj_t[(b0 + bo + 0) * 512 + j0 + j];
    float a1 = eproj_t[(b0 + bo + 1) * 512 + j0 + j];
    const float* w = g_Wcomb + j0 + j;
    for (int k = 0; k < 512; k++) {
        float wv = w[(size_t)k * 512];
        a0 += sc[bo + 0][k] * wv;
        a1 += sc[bo + 1][k] * wv;
    }
    g_xra[(b0 + bo + 0) * 512 + j0 + j] = a0;
    g_xra[(b0 + bo + 1) * 512 + j0 + j] = a1;
}

// ---------------- fused LayerNorm + GRU cell + alpha residual ---------------
__global__ __launch_bounds__(256) void gru_kernel(
    const float* __restrict__ xr_in,
    const float* __restrict__ h_in,
    float* __restrict__ h_out,
    float* __restrict__ xr_out,
    const float* __restrict__ Wih,
    const float* __restrict__ Whh,
    const float* __restrict__ bih,
    const float* __restrict__ bhh,
    const float* __restrict__ gamma,
    const float* __restrict__ beta,
    const float* __restrict__ alpha_p)
{
    int b0 = blockIdx.x * 4;
    int j0 = blockIdx.y * 32;
    int tid = threadIdx.x, lane = tid & 31, w = tid >> 5;
    __shared__ float sxin[4][512];
    __shared__ float shh [4][512];
    __shared__ float s_mu[4], s_rs[4];

    for (int i = tid; i < 2048; i += 256) sxin[i >> 9][i & 511] = xr_in[b0 * 512 + i];
    for (int i = tid; i < 2048; i += 256) shh [i >> 9][i & 511] = h_in [b0 * 512 + i];
    __syncthreads();

    if (w < 4) {
        float s1 = 0.f, s2 = 0.f;
        for (int k = lane; k < 512; k += 32) {
            float v = sxin[w][k];
            s1 += v; s2 += v * v;
        }
        for (int o = 16; o; o >>= 1) {
            s1 += __shfl_xor_sync(0xffffffffu, s1, o);
            s2 += __shfl_xor_sync(0xffffffffu, s2, o);
        }
        if (lane == 0) {
            float mu = s1 * (1.f / 512.f);
            float var = s2 * (1.f / 512.f) - mu * mu;
            s_mu[w] = mu;
            s_rs[w] = rsqrtf(var + 1e-5f);
        }
    }
    __syncthreads();
    for (int i = tid; i < 2048; i += 256) {
        int bb = i >> 9, k = i & 511;
        sxin[bb][k] = (sxin[bb][k] - s_mu[bb]) * s_rs[bb] * gamma[k] + beta[k];
    }
    __syncthreads();

    float alpha = *alpha_p;
#pragma unroll 1
    for (int i = 0; i < 16; i++) {
        int bb = i & 3;
        int jg = j0 + w * 4 + (i >> 2);
        const float* wr = Wih + (size_t)jg * 512;
        const float* wz = Wih + (size_t)(jg + 512) * 512;
        const float* wg = Wih + (size_t)(jg + 1024) * 512;
        const float* ur = Whh + (size_t)jg * 512;
        const float* uz = Whh + (size_t)(jg + 512) * 512;
        const float* ug = Whh + (size_t)(jg + 1024) * 512;
        float ir = 0.f, iz = 0.f, ig = 0.f, hr = 0.f, hz = 0.f, hg = 0.f;
        for (int k = lane; k < 512; k += 32) {
            float xv = sxin[bb][k], hv = shh[bb][k];
            ir += xv * wr[k]; iz += xv * wz[k]; ig += xv * wg[k];
            hr += hv * ur[k]; hz += hv * uz[k]; hg += hv * ug[k];
        }
        for (int o = 16; o; o >>= 1) {
            ir += __shfl_xor_sync(0xffffffffu, ir, o);
            iz += __shfl_xor_sync(0xffffffffu, iz, o);
            ig += __shfl_xor_sync(0xffffffffu, ig, o);
            hr += __shfl_xor_sync(0xffffffffu, hr, o);
            hz += __shfl_xor_sync(0xffffffffu, hz, o);
            hg += __shfl_xor_sync(0xffffffffu, hg, o);
        }
        if (lane == 0) {
            ir += bih[jg];        hr += bhh[jg];
            iz += bih[jg + 512];  hz += bhh[jg + 512];
            ig += bih[jg + 1024]; hg += bhh[jg + 1024];
            float r = 1.f / (1.f + expf(-(ir + hr)));
            float z = 1.f / (1.f + expf(-(iz + hz)));
            float g = tanhf(ig + r * hg);
            float hprev = shh[bb][jg];
            float hn = (1.f - z) * g + z * hprev;
            h_out [(b0 + bb) * 512 + jg] = hn;
            xr_out[(b0 + bb) * 512 + jg] = xr_in[(b0 + bb) * 512 + jg] + alpha * hn;
        }
    }
}

// ============================ host orchestration ============================
extern "C" void kernel_launch(void* const* d_in, const int* in_sizes, int n_in,
                              void* d_out, int out_size)
{
    const int*   x    = (const int*)  d_in[0];
    const float* enc  = (const float*)d_in[1];
    const float* h0   = (const float*)d_in[2];
    const int*   vlen = (const int*)  d_in[3];
    const float* emb  = (const float*)d_in[4];
    const float* Wq   = (const float*)d_in[5];
    const float* Wk   = (const float*)d_in[6];
    const float* Wv   = (const float*)d_in[7];
    const float* Wo   = (const float*)d_in[8];
    const float* Win  = (const float*)d_in[9];
    const float* lng  = (const float*)d_in[10];
    const float* lnb  = (const float*)d_in[11];
    const float* alph = (const float*)d_in[12];
    const float* Wih  = (const float*)d_in[13];
    const float* Whh  = (const float*)d_in[14];
    const float* bih  = (const float*)d_in[15];
    const float* bhh  = (const float*)d_in[16];
    const float* Wd   = (const float*)d_in[17];
    const float* bd   = (const float*)d_in[18];
    float* out = (float*)d_out;

    float *pKh, *pVh, *pEproj, *pWcomb, *pHA, *pHB, *pXra, *pXrb, *pYs;
    __nv_bfloat16 *pEncH, *pEncL, *pWktH, *pWktL, *pWvtH, *pWvtL, *pWintH, *pWintL;
    __nv_bfloat16 *pWdtH, *pWdtL, *pEsH, *pEsL, *pYsH, *pYsL;
    cudaGetSymbolAddress((void**)&pKh,    g_Kh);
    cudaGetSymbolAddress((void**)&pVh,    g_Vh);
    cudaGetSymbolAddress((void**)&pEproj, g_eproj);
    cudaGetSymbolAddress((void**)&pWcomb, g_Wcomb);
    cudaGetSymbolAddress((void**)&pHA,    g_hA);
    cudaGetSymbolAddress((void**)&pHB,    g_hB);
    cudaGetSymbolAddress((void**)&pXra,   g_xra);
    cudaGetSymbolAddress((void**)&pXrb,   g_xrb);
    cudaGetSymbolAddress((void**)&pYs,    g_ys);
    cudaGetSymbolAddress((void**)&pEncH,  g_enc_h);
    cudaGetSymbolAddress((void**)&pEncL,  g_enc_l);
    cudaGetSymbolAddress((void**)&pWktH,  g_Wkt_h);
    cudaGetSymbolAddress((void**)&pWktL,  g_Wkt_l);
    cudaGetSymbolAddress((void**)&pWvtH,  g_Wvt_h);
    cudaGetSymbolAddress((void**)&pWvtL,  g_Wvt_l);
    cudaGetSymbolAddress((void**)&pWintH, g_Wint_h);
    cudaGetSymbolAddress((void**)&pWintL, g_Wint_l);
    cudaGetSymbolAddress((void**)&pWdtH,  g_Wdt_h);
    cudaGetSymbolAddress((void**)&pWdtL,  g_Wdt_l);
    cudaGetSymbolAddress((void**)&pEsH,   g_eseq_h);
    cudaGetSymbolAddress((void**)&pEsL,   g_eseq_l);
    cudaGetSymbolAddress((void**)&pYsH,   g_ys_h);
    cudaGetSymbolAddress((void**)&pYsL,   g_ys_l);

    // h init
    copy_kernel<<<(LBH + 255) / 256, 256>>>(h0, pHA, LBH);

    // fp32 -> bf16 hi/lo conversions
    {
        int n4 = (B_ * TE * 2 * H_) / 4;
        aconv_kernel<<<(n4 + 255) / 256, 256>>>(enc, pEncH, pEncL, n4);
    }
    tconv_kernel<<<dim3(H_ / 32, 2 * H_ / 32), dim3(32, 8)>>>(Wk, 2 * H_, H_, 0, pWktH, pWktL);
    tconv_kernel<<<dim3(H_ / 32, 2 * H_ / 32), dim3(32, 8)>>>(Wv, 2 * H_, H_, 0, pWvtH, pWvtL);
    tconv_kernel<<<dim3(H_ / 32, H_ / 32), dim3(32, 8)>>>(Win, H_, H_, 512, pWintH, pWintL);
    tconv_kernel<<<dim3(V_ / 32, H_ / 32), dim3(32, 8)>>>(Wd, H_, V_, 0, pWdtH, pWdtL);
    gather_emb_kernel<<<TD * B_, 128>>>(x, emb);

    // K/V projections via HMMA tensor cores
    mma_gemm_kernel<<<dim3(H_ / 128, (B_ * TE) / 128), 256>>>(
        B_ * TE, H_, 2 * H_, pEncH, pEncL, pWktH, pWktL, pKh, nullptr, 0);
    mma_gemm_kernel<<<dim3(H_ / 128, (B_ * TE) / 128), 256>>>(
        B_ * TE, H_, 2 * H_, pEncH, pEncL, pWvtH, pWvtL, pVh, nullptr, 0);
    transpose_k_kernel<<<dim3(B_ * NH, TE / 32, DH / 32), dim3(32, 8)>>>();

    // eproj = eseq @ W_in[512:]
    mma_gemm_kernel<<<dim3(H_ / 128, (TD * B_) / 128), 256>>>(
        TD * B_, H_, E_, pEsH, pEsL, pWintH, pWintL, pEproj, nullptr, 0);

    // W_comb = W_o @ W_in[:512] (small, fp32 SIMT)
    sgemm_kernel<<<dim3(H_ / 128, H_ / 128), 256>>>(
        H_, H_, H_, Wo, H_, Win, H_, pWcomb, nullptr, 0);

    // sequential decode scan
    for (int t = 0; t < TD; t++) {
        const float* hin  = (t & 1) ? pHB : pHA;
        float*       hout = (t & 1) ? pHA : pHB;

        attn_kernel<<<B_ * NH, 256>>>(hin + (L_ - 1) * B_ * H_, Wq, vlen);
        xr_kernel<<<dim3(8, 4), 256>>>(pEproj + (size_t)t * B_ * H_);
        gru_kernel<<<dim3(8, 16), 256>>>(
            pXra, hin, hout, pXrb,
            Wih, Whh, bih, bhh, lng, lnb, alph + 0);
        gru_kernel<<<dim3(8, 16), 256>>>(
            pXrb, hin + B_ * H_, hout + B_ * H_, pYs + (size_t)t * B_ * H_,
            Wih + 3 * H_ * H_, Whh + 3 * H_ * H_, bih + 3 * H_, bhh + 3 * H_,
            lng + H_, lnb + H_, alph + 1);
    }

    // ys -> bf16 hi/lo, then logits via HMMA tensor cores
    {
        int n4 = (TD * B_ * H_) / 4;
        aconv_kernel<<<(n4 + 255) / 256, 256>>>(pYs, pYsH, pYsL, n4);
    }
    mma_gemm_kernel<<<dim3(V_ / 128, (TD * B_) / 128), 256>>>(
        TD * B_, V_, H_, pYsH, pYsL, pWdtH, pWdtL, out, bd, 1);

    // final hidden state (t=63 odd -> final state lives in g_hA)
    if (out_size >= BTV + LBH)
        copy_kernel<<<(LBH + 255) / 256, 256>>>(pHA, out + BTV, LBH);
}

// round 5
// speedup vs baseline: 3.0941x; 2.8901x over previous
#include <cuda_runtime.h>
#include <cuda_bf16.h>
#include <math.h>
#include <stdint.h>

constexpr int B_  = 32;
constexpr int TD  = 64;
constexpr int TE  = 256;
constexpr int H_  = 512;
constexpr int E_  = 512;
constexpr int V_  = 32000;
constexpr int L_  = 2;
constexpr int NH  = 8;
constexpr int DH  = 64;
constexpr int BTV = B_ * TD * V_;
constexpr int LBH = L_ * B_ * H_;

constexpr int NBLK = 128;   // persistent scan blocks (<= 148 SMs, 1/SM)
constexpr int NTHR = 512;

// ---------------- scratch (device globals) ----------------------------------
__device__ __align__(16) float g_Kh  [B_ * TE * H_];
__device__ __align__(16) float g_Kh2 [B_ * NH * DH * TE];
__device__ __align__(16) float g_Vh  [B_ * TE * H_];
__device__ __align__(16) float g_eproj[TD * B_ * H_];
__device__ __align__(16) float g_Wcomb[H_ * H_];
__device__ __align__(16) float g_Wcombt[H_ * H_];
__device__ __align__(16) float g_hA[LBH];
__device__ __align__(16) float g_hB[LBH];
__device__ __align__(16) float g_ctx[B_ * H_];
__device__ __align__(16) float g_xra[B_ * H_];
__device__ __align__(16) float g_xrb[B_ * H_];
__device__ int g_bar;

__device__ __align__(16) __nv_bfloat16 g_enc_h [B_ * TE * 2 * H_];
__device__ __align__(16) __nv_bfloat16 g_enc_l [B_ * TE * 2 * H_];
__device__ __align__(16) __nv_bfloat16 g_Wkt_h [H_ * 2 * H_];
__device__ __align__(16) __nv_bfloat16 g_Wkt_l [H_ * 2 * H_];
__device__ __align__(16) __nv_bfloat16 g_Wvt_h [H_ * 2 * H_];
__device__ __align__(16) __nv_bfloat16 g_Wvt_l [H_ * 2 * H_];
__device__ __align__(16) __nv_bfloat16 g_Wint_h[H_ * H_];
__device__ __align__(16) __nv_bfloat16 g_Wint_l[H_ * H_];
__device__ __align__(16) __nv_bfloat16 g_Wdt_h [V_ * H_];
__device__ __align__(16) __nv_bfloat16 g_Wdt_l [V_ * H_];
__device__ __align__(16) __nv_bfloat16 g_eseq_h[TD * B_ * E_];
__device__ __align__(16) __nv_bfloat16 g_eseq_l[TD * B_ * E_];
__device__ __align__(16) __nv_bfloat16 g_ys_h  [TD * B_ * H_];
__device__ __align__(16) __nv_bfloat16 g_ys_l  [TD * B_ * H_];

// ======================= mma.sync helpers ====================================
__device__ __forceinline__ uint32_t smem_u32(const void* p) {
    uint32_t a;
    asm("{ .reg .u64 t; cvta.to.shared.u64 t, %1; cvt.u32.u64 %0, t; }"
        : "=r"(a) : "l"(p));
    return a;
}
__device__ __forceinline__ void ldsm4(uint32_t (&r)[4], uint32_t addr) {
    asm volatile("ldmatrix.sync.aligned.m8n8.x4.shared.b16 {%0,%1,%2,%3}, [%4];"
        : "=r"(r[0]), "=r"(r[1]), "=r"(r[2]), "=r"(r[3]) : "r"(addr));
}
__device__ __forceinline__ void mma16816(float (&d)[4], const uint32_t (&a)[4],
                                         uint32_t b0, uint32_t b1) {
    asm volatile(
        "mma.sync.aligned.m16n8k16.row.col.f32.bf16.bf16.f32 "
        "{%0,%1,%2,%3}, {%4,%5,%6,%7}, {%8,%9}, {%0,%1,%2,%3};"
        : "+f"(d[0]), "+f"(d[1]), "+f"(d[2]), "+f"(d[3])
        : "r"(a[0]), "r"(a[1]), "r"(a[2]), "r"(a[3]), "r"(b0), "r"(b1));
}

// ============ HMMA compensated-bf16 GEMM (unchanged from R4) ================
constexpr int BKg  = 32;
constexpr int LDSg = BKg + 8;

__global__ __launch_bounds__(256) void mma_gemm_kernel(
    int M, int N, int K,
    const __nv_bfloat16* __restrict__ Ah, const __nv_bfloat16* __restrict__ Al,
    const __nv_bfloat16* __restrict__ Bh, const __nv_bfloat16* __restrict__ Bl,
    float* __restrict__ C, const float* __restrict__ bias, int mode)
{
    __shared__ __nv_bfloat16 sAh[128 * LDSg], sAl[128 * LDSg];
    __shared__ __nv_bfloat16 sBh[128 * LDSg], sBl[128 * LDSg];

    const int tid = threadIdx.x, lane = tid & 31, wid = tid >> 5;
    const int wm = wid >> 1, wn = wid & 1;
    const int n0 = blockIdx.x * 128, m0 = blockIdx.y * 128;

    float acc[2][8][4];
#pragma unroll
    for (int i = 0; i < 2; i++)
#pragma unroll
        for (int j = 0; j < 8; j++)
#pragma unroll
            for (int k = 0; k < 4; k++) acc[i][j][k] = 0.f;

    const int lrow = tid >> 2;
    const int lcol = (tid & 3) * 8;

    for (int kb = 0; kb < K; kb += BKg) {
        __syncthreads();
#pragma unroll
        for (int h = 0; h < 2; h++) {
            int row = lrow + h * 64;
            size_t ga = (size_t)(m0 + row) * K + kb + lcol;
            size_t gb = (size_t)(n0 + row) * K + kb + lcol;
            uint32_t so = row * LDSg + lcol;
            *(uint4*)&sAh[so] = *(const uint4*)(Ah + ga);
            *(uint4*)&sAl[so] = *(const uint4*)(Al + ga);
            *(uint4*)&sBh[so] = *(const uint4*)(Bh + gb);
            *(uint4*)&sBl[so] = *(const uint4*)(Bl + gb);
        }
        __syncthreads();

#pragma unroll
        for (int ks = 0; ks < BKg; ks += 16) {
            uint32_t ah[2][4], al[2][4];
            const uint32_t fcol = ks + (lane >> 4) * 8;
#pragma unroll
            for (int mi = 0; mi < 2; mi++) {
                uint32_t arow = wm * 32 + mi * 16 + (lane & 15);
                ldsm4(ah[mi], smem_u32(&sAh[arow * LDSg + fcol]));
                ldsm4(al[mi], smem_u32(&sAl[arow * LDSg + fcol]));
            }
#pragma unroll
            for (int nj = 0; nj < 4; nj++) {
                uint32_t brow = wn * 64 + nj * 16 + (lane & 15);
                uint32_t bh[4], bl[4];
                ldsm4(bh, smem_u32(&sBh[brow * LDSg + fcol]));
                ldsm4(bl, smem_u32(&sBl[brow * LDSg + fcol]));
#pragma unroll
                for (int mi = 0; mi < 2; mi++) {
                    mma16816(acc[mi][2 * nj],     ah[mi], bh[0], bh[2]);
                    mma16816(acc[mi][2 * nj + 1], ah[mi], bh[1], bh[3]);
                    mma16816(acc[mi][2 * nj],     ah[mi], bl[0], bl[2]);
                    mma16816(acc[mi][2 * nj + 1], ah[mi], bl[1], bl[3]);
                    mma16816(acc[mi][2 * nj],     al[mi], bh[0], bh[2]);
                    mma16816(acc[mi][2 * nj + 1], al[mi], bh[1], bh[3]);
                }
            }
        }
    }

#pragma unroll
    for (int mi = 0; mi < 2; mi++) {
        int row = m0 + wm * 32 + mi * 16 + (lane >> 2);
#pragma unroll
        for (int nt = 0; nt < 8; nt++) {
            int col = n0 + wn * 64 + nt * 8 + (lane & 3) * 2;
            float bb0 = bias ? bias[col] : 0.f;
            float bb1 = bias ? bias[col + 1] : 0.f;
            float2 v0 = make_float2(acc[mi][nt][0] + bb0, acc[mi][nt][1] + bb1);
            float2 v1 = make_float2(acc[mi][nt][2] + bb0, acc[mi][nt][3] + bb1);
            if (mode == 0) {
                *(float2*)&C[(size_t)row * N + col] = v0;
                *(float2*)&C[(size_t)(row + 8) * N + col] = v1;
            } else {
                int t0 = row >> 5, b0v_ = row & 31;
                int t1 = (row + 8) >> 5, b1v_ = (row + 8) & 31;
                *(float2*)&C[(size_t)b0v_ * (TD * V_) + (size_t)t0 * V_ + col] = v0;
                *(float2*)&C[(size_t)b1v_ * (TD * V_) + (size_t)t1 * V_ + col] = v1;
            }
        }
    }
}

// ---------------- conversions ------------------------------------------------
__device__ __forceinline__ void bsplit(float x, __nv_bfloat16& h, __nv_bfloat16& l) {
    h = __float2bfloat16(x);
    l = __float2bfloat16(x - __bfloat162float(h));
}

__global__ void aconv_kernel(const float* __restrict__ src,
                             __nv_bfloat16* __restrict__ oh,
                             __nv_bfloat16* __restrict__ ol, int n4)
{
    int i = blockIdx.x * blockDim.x + threadIdx.x;
    if (i >= n4) return;
    float4 v = ((const float4*)src)[i];
    __nv_bfloat16 h0, h1, h2, h3, l0, l1, l2, l3;
    bsplit(v.x, h0, l0); bsplit(v.y, h1, l1);
    bsplit(v.z, h2, l2); bsplit(v.w, h3, l3);
    ((__nv_bfloat162*)oh)[2 * i]     = __nv_bfloat162(h0, h1);
    ((__nv_bfloat162*)oh)[2 * i + 1] = __nv_bfloat162(h2, h3);
    ((__nv_bfloat162*)ol)[2 * i]     = __nv_bfloat162(l0, l1);
    ((__nv_bfloat162*)ol)[2 * i + 1] = __nv_bfloat162(l2, l3);
}

__global__ void tconv_kernel(const float* __restrict__ W, int K, int N, int row_off,
                             __nv_bfloat16* __restrict__ oh, __nv_bfloat16* __restrict__ ol)
{
    __shared__ float t[32][33];
    int n0 = blockIdx.x * 32, k0 = blockIdx.y * 32;
    for (int ky = threadIdx.y; ky < 32; ky += 8)
        t[ky][threadIdx.x] = W[(size_t)(row_off + k0 + ky) * N + n0 + threadIdx.x];
    __syncthreads();
    for (int ny = threadIdx.y; ny < 32; ny += 8) {
        float v = t[threadIdx.x][ny];
        __nv_bfloat16 h, l; bsplit(v, h, l);
        size_t o = (size_t)(n0 + ny) * K + k0 + threadIdx.x;
        oh[o] = h; ol[o] = l;
    }
}

// ---------------- fp32 SIMT GEMM (Wcomb only) --------------------------------
__global__ __launch_bounds__(256) void sgemm_kernel(
    int M, int N, int K,
    const float* __restrict__ A, int lda,
    const float* __restrict__ B, int ldb,
    float* __restrict__ C,
    const float* __restrict__ bias, int mode)
{
    __shared__ float As[8][132];
    __shared__ float Bs[8][132];
    const int tid = threadIdx.x;
    const int bx = blockIdx.x, by = blockIdx.y;
    const float* Aptr = A + (size_t)(by * 128 + (tid >> 1)) * lda + (tid & 1) * 4;
    const float* Bptr = B + (size_t)(tid >> 5) * ldb + bx * 128 + (tid & 31) * 4;
    const int ty = tid >> 4, tx = tid & 15;
    float acc[8][8];
#pragma unroll
    for (int i = 0; i < 8; i++)
#pragma unroll
        for (int j = 0; j < 8; j++) acc[i][j] = 0.f;
    for (int k0 = 0; k0 < K; k0 += 8) {
        float4 av = *(const float4*)(Aptr + k0);
        float4 bv = *(const float4*)(Bptr + (size_t)k0 * ldb);
        __syncthreads();
        const int ar_ = tid >> 1, ac_ = (tid & 1) * 4;
        As[ac_ + 0][ar_] = av.x; As[ac_ + 1][ar_] = av.y;
        As[ac_ + 2][ar_] = av.z; As[ac_ + 3][ar_] = av.w;
        *(float4*)&Bs[tid >> 5][(tid & 31) * 4] = bv;
        __syncthreads();
#pragma unroll
        for (int kk = 0; kk < 8; kk++) {
            float ar[8], br[8];
            *(float4*)(ar)     = *(float4*)&As[kk][ty * 4];
            *(float4*)(ar + 4) = *(float4*)&As[kk][ty * 4 + 64];
            *(float4*)(br)     = *(float4*)&Bs[kk][tx * 4];
            *(float4*)(br + 4) = *(float4*)&Bs[kk][tx * 4 + 64];
#pragma unroll
            for (int i = 0; i < 8; i++)
#pragma unroll
                for (int j = 0; j < 8; j++) acc[i][j] += ar[i] * br[j];
        }
    }
#pragma unroll
    for (int i = 0; i < 8; i++) {
        int m = by * 128 + ty * 4 + (i & 3) + (i >> 2) * 64;
#pragma unroll
        for (int j = 0; j < 8; j++) {
            int n = bx * 128 + tx * 4 + (j & 3) + (j >> 2) * 64;
            float v = acc[i][j] + (bias ? bias[n] : 0.f);
            if (mode == 0) C[(size_t)m * N + n] = v;
        }
    }
}

// ---------------- transposes -------------------------------------------------
__global__ void transpose_k_kernel()
{
    __shared__ float t[32][33];
    int bh = blockIdx.x;
    int b = bh >> 3, h = bh & 7;
    int s0 = blockIdx.y * 32, d0 = blockIdx.z * 32;
    for (int yy = threadIdx.y; yy < 32; yy += 8)
        t[yy][threadIdx.x] = g_Kh[((size_t)(b * 256 + s0 + yy) * 8 + h) * 64 + d0 + threadIdx.x];
    __syncthreads();
    for (int yy = threadIdx.y; yy < 32; yy += 8)
        g_Kh2[((size_t)(bh) * 64 + d0 + yy) * 256 + s0 + threadIdx.x] = t[threadIdx.x][yy];
}

__global__ void transpose512_kernel(const float* __restrict__ src, float* __restrict__ dst)
{
    __shared__ float t[32][33];
    int x0 = blockIdx.x * 32, y0 = blockIdx.y * 32;
    for (int yy = threadIdx.y; yy < 32; yy += 8)
        t[yy][threadIdx.x] = src[(size_t)(y0 + yy) * 512 + x0 + threadIdx.x];
    __syncthreads();
    for (int yy = threadIdx.y; yy < 32; yy += 8)
        dst[(size_t)(x0 + yy) * 512 + y0 + threadIdx.x] = t[threadIdx.x][yy];
}

// ---------------- embedding gather -> bf16 hi/lo -----------------------------
__global__ void gather_emb_kernel(const int* __restrict__ x, const float* __restrict__ emb)
{
    int r = blockIdx.x;
    int t = r >> 5, b = r & 31;
    int tok = x[b * TD + t];
    const float* src = emb + (size_t)tok * E_;
    for (int i = threadIdx.x; i < E_; i += blockDim.x) {
        __nv_bfloat16 h, l; bsplit(src[i], h, l);
        g_eseq_h[(size_t)r * E_ + i] = h;
        g_eseq_l[(size_t)r * E_ + i] = l;
    }
}

__global__ void copy_kernel(const float* __restrict__ src, float* __restrict__ dst, int n)
{
    int i = blockIdx.x * blockDim.x + threadIdx.x;
    if (i < n) dst[i] = src[i];
}

__global__ void reset_kernel() { g_bar = 0; }

// =================== PERSISTENT SCAN KERNEL ==================================
// smem layout (floats):
constexpr int OFF_W   = 0;        // 24576: weights [2l][4jl][6g][512k]
constexpr int OFF_BF  = 24576;    // 16640: buffer [32b][520]
constexpr int OFF_GP  = 41216;    // 3072:  gate partials (2 sets x 1536)
constexpr int OFF_AT  = 44288;    // 2176:  attention arrays (2 groups x 1088)
constexpr int OFF_MU  = 46464;    // 32
constexpr int OFF_RS  = 46496;    // 32
constexpr int OFF_HPV = 46528;    // 128
constexpr int SCAN_SMEM_FLOATS = 46656;
constexpr int BFS = 520;          // bf row stride

__device__ __forceinline__ void grid_bar(int& epoch) {
    __syncthreads();
    epoch += NBLK;
    if (threadIdx.x == 0) {
        __threadfence();
        atomicAdd(&g_bar, 1);
        while (*(volatile int*)&g_bar < epoch) __nanosleep(32);
        __threadfence();
    }
    __syncthreads();
}

__global__ __launch_bounds__(NTHR, 1) void scan_kernel(
    const float* __restrict__ Wq,  const int* __restrict__ vlen,
    const float* __restrict__ Wih, const float* __restrict__ Whh,
    const float* __restrict__ bih, const float* __restrict__ bhh,
    const float* __restrict__ lng, const float* __restrict__ lnb,
    const float* __restrict__ alph)
{
    extern __shared__ float sm[];
    float* w   = sm + OFF_W;
    float* bf  = sm + OFF_BF;
    float* gp  = sm + OFF_GP;
    float* at  = sm + OFF_AT;
    float* mu  = sm + OFF_MU;
    float* rs  = sm + OFF_RS;
    float* hpv = sm + OFF_HPV;

    const int tid = threadIdx.x, lane = tid & 31, wid = tid >> 5;
    const int blk = blockIdx.x;
    int epoch = 0;

    // ---- load GRU weights once: w[((l*4+jl)*6+g)*512+k] ----
    for (int i = tid; i < 24576; i += NTHR) {
        int unit = i >> 9, k = i & 511;
        int l = unit / 24, rem = unit % 24;
        int jl = rem / 6, g = rem % 6;
        int jg = blk * 4 + jl;
        const float* src = (g < 3)
            ? (Wih + ((size_t)l * 3 * 512 + g * 512 + jg) * 512)
            : (Whh + ((size_t)l * 3 * 512 + (g - 3) * 512 + jg) * 512);
        w[i] = src[k];
    }
    __syncthreads();

    for (int t = 0; t < TD; t++) {
        const float* hin  = (t & 1) ? g_hB : g_hA;
        float*       hout = (t & 1) ? g_hA : g_hB;

        // ================= phase 1: attention (2 bh-units per block) ========
        {
            int grp = tid >> 8, lt = tid & 255;
            int u = blk * 2 + grp;
            int b = u >> 3, h = u & 7;
            float* sh_ = at + grp * 1088;
            float* sq_ = sh_ + 512;
            float* sp_ = sq_ + 64;
            float* rd_ = sp_ + 256;
            const float* hlast = hin + (L_ - 1) * B_ * H_ + b * 512;

            sh_[lt] = hlast[lt];
            sh_[lt + 256] = hlast[lt + 256];
            __syncthreads();

            int d = lt & 63, c = lt >> 6;
            {
                float acc = 0.f;
                const float* wq = Wq + h * 64 + d;
#pragma unroll 8
                for (int k = c * 128; k < c * 128 + 128; k++)
                    acc += sh_[k] * wq[(size_t)k * 512];
                rd_[lt] = acc;
            }
            __syncthreads();
            if (lt < 64) sq_[lt] = rd_[lt] + rd_[lt + 64] + rd_[lt + 128] + rd_[lt + 192];
            __syncthreads();

            float sc = -1e6f;
            int vl = vlen[b];
            if (lt < vl) {
                float a = 0.f;
                const float* kp = g_Kh2 + (size_t)u * 64 * 256 + lt;
#pragma unroll 8
                for (int dd = 0; dd < 64; dd++) a += sq_[dd] * kp[dd * 256];
                sc = a * 0.125f;
            }
            rd_[lt] = sc; __syncthreads();
            for (int off = 128; off > 0; off >>= 1) {
                if (lt < off) rd_[lt] = fmaxf(rd_[lt], rd_[lt + off]);
                __syncthreads();
            }
            float mx = rd_[0];
            __syncthreads();
            float p = expf(sc - mx);
            rd_[lt] = p; __syncthreads();
            for (int off = 128; off > 0; off >>= 1) {
                if (lt < off) rd_[lt] += rd_[lt + off];
                __syncthreads();
            }
            float sum = rd_[0];
            sp_[lt] = p / sum;
            __syncthreads();

            {
                float a = 0.f;
                const float* vp = g_Vh + ((size_t)(b * 256 + c * 64) * 8 + h) * 64 + d;
#pragma unroll 8
                for (int ss = 0; ss < 64; ss++) a += sp_[c * 64 + ss] * vp[(size_t)ss * 512];
                rd_[lt] = a;
            }
            __syncthreads();
            if (lt < 64)
                g_ctx[b * 512 + h * 64 + lt] =
                    rd_[lt] + rd_[lt + 64] + rd_[lt + 128] + rd_[lt + 192];
        }
        grid_bar(epoch);

        // ================= phase 2: xr = ctx @ Wcomb + eproj[t] =============
        for (int i = tid; i < 16384; i += NTHR) {
            int b = i >> 9, k = i & 511;
            bf[b * BFS + k] = g_ctx[i];
        }
        __syncthreads();
        {
            int jl = wid >> 2, kq = wid & 3;
            int jg = blk * 4 + jl;
            const float* wc = g_Wcombt + (size_t)jg * 512 + kq * 128;
            const float* xrow = bf + lane * BFS + kq * 128;
            float acc = 0.f;
#pragma unroll
            for (int k0 = 0; k0 < 128; k0 += 4) {
                float4 wv = *(const float4*)(wc + k0);
                float4 xv = *(const float4*)(xrow + k0);
                acc += wv.x * xv.x + wv.y * xv.y + wv.z * xv.z + wv.w * xv.w;
            }
            gp[(jl * 4 + kq) * 32 + lane] = acc;
        }
        __syncthreads();
        if (tid < 128) {
            int jl = tid >> 5, b = tid & 31, jg = blk * 4 + jl;
            float v = gp[(jl * 4 + 0) * 32 + b] + gp[(jl * 4 + 1) * 32 + b]
                    + gp[(jl * 4 + 2) * 32 + b] + gp[(jl * 4 + 3) * 32 + b];
            g_xra[b * 512 + jg] = v + g_eproj[(size_t)(t * B_ + b) * H_ + jg];
        }
        grid_bar(epoch);

        // ================= phases 3,4: GRU layers ===========================
        for (int l = 0; l < 2; l++) {
            const float* xr = (l == 0) ? g_xra : g_xrb;
            const float* hsrc = hin + l * B_ * H_;
            float* hdst = hout + l * B_ * H_;

            // load h into bf
            for (int i = tid; i < 16384; i += NTHR) {
                int b = i >> 9, k = i & 511;
                bf[b * BFS + k] = hsrc[i];
            }
            __syncthreads();
            if (tid < 128) {
                int jl = tid >> 5, b = tid & 31;
                hpv[tid] = bf[b * BFS + blk * 4 + jl];
            }
            // hh sub-phase -> gp set 0
            {
                int jl = wid >> 2, kq = wid & 3;
                const float* wb = w + (((l * 4 + jl) * 6) + 3) * 512 + kq * 128;
                const float* xrow = bf + lane * BFS + kq * 128;
                float a0 = 0.f, a1 = 0.f, a2 = 0.f;
#pragma unroll
                for (int k0 = 0; k0 < 128; k0 += 4) {
                    float4 xv = *(const float4*)(xrow + k0);
                    float4 w0 = *(const float4*)(wb + k0);
                    float4 w1 = *(const float4*)(wb + 512 + k0);
                    float4 w2 = *(const float4*)(wb + 1024 + k0);
                    a0 += w0.x * xv.x + w0.y * xv.y + w0.z * xv.z + w0.w * xv.w;
                    a1 += w1.x * xv.x + w1.y * xv.y + w1.z * xv.z + w1.w * xv.w;
                    a2 += w2.x * xv.x + w2.y * xv.y + w2.z * xv.z + w2.w * xv.w;
                }
                gp[((jl * 3 + 0) * 4 + kq) * 32 + lane] = a0;
                gp[((jl * 3 + 1) * 4 + kq) * 32 + lane] = a1;
                gp[((jl * 3 + 2) * 4 + kq) * 32 + lane] = a2;
            }
            __syncthreads();
            // LN stats over xr rows (2 rows per warp)
            {
#pragma unroll
                for (int rr = 0; rr < 2; rr++) {
                    int b = wid * 2 + rr;
                    float s1 = 0.f, s2 = 0.f;
#pragma unroll
                    for (int kk = 0; kk < 16; kk++) {
                        float v = xr[b * 512 + lane + kk * 32];
                        s1 += v; s2 += v * v;
                    }
#pragma unroll
                    for (int o = 16; o; o >>= 1) {
                        s1 += __shfl_xor_sync(0xffffffffu, s1, o);
                        s2 += __shfl_xor_sync(0xffffffffu, s2, o);
                    }
                    if (lane == 0) {
                        float m = s1 * (1.f / 512.f);
                        float var = s2 * (1.f / 512.f) - m * m;
                        mu[b] = m;
                        rs[b] = rsqrtf(var + 1e-5f);
                    }
                }
            }
            __syncthreads();
            // normalize xr into bf
            for (int i = tid; i < 16384; i += NTHR) {
                int b = i >> 9, k = i & 511;
                bf[b * BFS + k] = (xr[i] - mu[b]) * rs[b] * lng[l * 512 + k] + lnb[l * 512 + k];
            }
            __syncthreads();
            // ih sub-phase -> gp set 1
            {
                int jl = wid >> 2, kq = wid & 3;
                const float* wb = w + ((l * 4 + jl) * 6) * 512 + kq * 128;
                const float* xrow = bf + lane * BFS + kq * 128;
                float a0 = 0.f, a1 = 0.f, a2 = 0.f;
#pragma unroll
                for (int k0 = 0; k0 < 128; k0 += 4) {
                    float4 xv = *(const float4*)(xrow + k0);
                    float4 w0 = *(const float4*)(wb + k0);
                    float4 w1 = *(const float4*)(wb + 512 + k0);
                    float4 w2 = *(const float4*)(wb + 1024 + k0);
                    a0 += w0.x * xv.x + w0.y * xv.y + w0.z * xv.z + w0.w * xv.w;
                    a1 += w1.x * xv.x + w1.y * xv.y + w1.z * xv.z + w1.w * xv.w;
                    a2 += w2.x * xv.x + w2.y * xv.y + w2.z * xv.z + w2.w * xv.w;
                }
                gp[1536 + ((jl * 3 + 0) * 4 + kq) * 32 + lane] = a0;
                gp[1536 + ((jl * 3 + 1) * 4 + kq) * 32 + lane] = a1;
                gp[1536 + ((jl * 3 + 2) * 4 + kq) * 32 + lane] = a2;
            }
            __syncthreads();
            // combine
            if (tid < 128) {
                int jl = tid >> 5, b = tid & 31, jg = blk * 4 + jl;
                float hr = 0.f, hz = 0.f, hg = 0.f, ir = 0.f, iz = 0.f, ig = 0.f;
#pragma unroll
                for (int kq = 0; kq < 4; kq++) {
                    hr += gp[((jl * 3 + 0) * 4 + kq) * 32 + b];
                    hz += gp[((jl * 3 + 1) * 4 + kq) * 32 + b];
                    hg += gp[((jl * 3 + 2) * 4 + kq) * 32 + b];
                    ir += gp[1536 + ((jl * 3 + 0) * 4 + kq) * 32 + b];
                    iz += gp[1536 + ((jl * 3 + 1) * 4 + kq) * 32 + b];
                    ig += gp[1536 + ((jl * 3 + 2) * 4 + kq) * 32 + b];
                }
                ir += bih[l * 1536 + jg];        hr += bhh[l * 1536 + jg];
                iz += bih[l * 1536 + 512 + jg];  hz += bhh[l * 1536 + 512 + jg];
                ig += bih[l * 1536 + 1024 + jg]; hg += bhh[l * 1536 + 1024 + jg];
                float r = 1.f / (1.f + expf(-(ir + hr)));
                float z = 1.f / (1.f + expf(-(iz + hz)));
                float g = tanhf(ig + r * hg);
                float hn = (1.f - z) * g + z * hpv[tid];
                hdst[b * 512 + jg] = hn;
                float yv = xr[b * 512 + jg] + alph[l] * hn;
                if (l == 0) {
                    g_xrb[b * 512 + jg] = yv;
                } else {
                    __nv_bfloat16 yh, yl; bsplit(yv, yh, yl);
                    size_t o = (size_t)(t * B_ + b) * 512 + jg;
                    g_ys_h[o] = yh;
                    g_ys_l[o] = yl;
                }
            }
            grid_bar(epoch);
        }
    }
}

// ============================ host orchestration ============================
extern "C" void kernel_launch(void* const* d_in, const int* in_sizes, int n_in,
                              void* d_out, int out_size)
{
    const int*   x    = (const int*)  d_in[0];
    const float* enc  = (const float*)d_in[1];
    const float* h0   = (const float*)d_in[2];
    const int*   vlen = (const int*)  d_in[3];
    const float* emb  = (const float*)d_in[4];
    const float* Wq   = (const float*)d_in[5];
    const float* Wk   = (const float*)d_in[6];
    const float* Wv   = (const float*)d_in[7];
    const float* Wo   = (const float*)d_in[8];
    const float* Win  = (const float*)d_in[9];
    const float* lng  = (const float*)d_in[10];
    const float* lnb  = (const float*)d_in[11];
    const float* alph = (const float*)d_in[12];
    const float* Wih  = (const float*)d_in[13];
    const float* Whh  = (const float*)d_in[14];
    const float* bih  = (const float*)d_in[15];
    const float* bhh  = (const float*)d_in[16];
    const float* Wd   = (const float*)d_in[17];
    const float* bd   = (const float*)d_in[18];
    float* out = (float*)d_out;

    cudaFuncSetAttribute(scan_kernel, cudaFuncAttributeMaxDynamicSharedMemorySize,
                         SCAN_SMEM_FLOATS * 4);

    float *pKh, *pVh, *pEproj, *pWcomb, *pWcombT, *pHA;
    __nv_bfloat16 *pEncH, *pEncL, *pWktH, *pWktL, *pWvtH, *pWvtL, *pWintH, *pWintL;
    __nv_bfloat16 *pWdtH, *pWdtL, *pEsH, *pEsL, *pYsH, *pYsL;
    cudaGetSymbolAddress((void**)&pKh,     g_Kh);
    cudaGetSymbolAddress((void**)&pVh,     g_Vh);
    cudaGetSymbolAddress((void**)&pEproj,  g_eproj);
    cudaGetSymbolAddress((void**)&pWcomb,  g_Wcomb);
    cudaGetSymbolAddress((void**)&pWcombT, g_Wcombt);
    cudaGetSymbolAddress((void**)&pHA,     g_hA);
    cudaGetSymbolAddress((void**)&pEncH,   g_enc_h);
    cudaGetSymbolAddress((void**)&pEncL,   g_enc_l);
    cudaGetSymbolAddress((void**)&pWktH,   g_Wkt_h);
    cudaGetSymbolAddress((void**)&pWktL,   g_Wkt_l);
    cudaGetSymbolAddress((void**)&pWvtH,   g_Wvt_h);
    cudaGetSymbolAddress((void**)&pWvtL,   g_Wvt_l);
    cudaGetSymbolAddress((void**)&pWintH,  g_Wint_h);
    cudaGetSymbolAddress((void**)&pWintL,  g_Wint_l);
    cudaGetSymbolAddress((void**)&pWdtH,   g_Wdt_h);
    cudaGetSymbolAddress((void**)&pWdtL,   g_Wdt_l);
    cudaGetSymbolAddress((void**)&pEsH,    g_eseq_h);
    cudaGetSymbolAddress((void**)&pEsL,    g_eseq_l);
    cudaGetSymbolAddress((void**)&pYsH,    g_ys_h);
    cudaGetSymbolAddress((void**)&pYsL,    g_ys_l);

    // h init + barrier reset
    copy_kernel<<<(LBH + 255) / 256, 256>>>(h0, pHA, LBH);
    reset_kernel<<<1, 1>>>();

    // conversions
    {
        int n4 = (B_ * TE * 2 * H_) / 4;
        aconv_kernel<<<(n4 + 255) / 256, 256>>>(enc, pEncH, pEncL, n4);
    }
    tconv_kernel<<<dim3(H_ / 32, 2 * H_ / 32), dim3(32, 8)>>>(Wk, 2 * H_, H_, 0, pWktH, pWktL);
    tconv_kernel<<<dim3(H_ / 32, 2 * H_ / 32), dim3(32, 8)>>>(Wv, 2 * H_, H_, 0, pWvtH, pWvtL);
    tconv_kernel<<<dim3(H_ / 32, H_ / 32), dim3(32, 8)>>>(Win, H_, H_, 512, pWintH, pWintL);
    tconv_kernel<<<dim3(V_ / 32, H_ / 32), dim3(32, 8)>>>(Wd, H_, V_, 0, pWdtH, pWdtL);
    gather_emb_kernel<<<TD * B_, 128>>>(x, emb);

    // K/V projections (HMMA)
    mma_gemm_kernel<<<dim3(H_ / 128, (B_ * TE) / 128), 256>>>(
        B_ * TE, H_, 2 * H_, pEncH, pEncL, pWktH, pWktL, pKh, nullptr, 0);
    mma_gemm_kernel<<<dim3(H_ / 128, (B_ * TE) / 128), 256>>>(
        B_ * TE, H_, 2 * H_, pEncH, pEncL, pWvtH, pWvtL, pVh, nullptr, 0);
    transpose_k_kernel<<<dim3(B_ * NH, TE / 32, DH / 32), dim3(32, 8)>>>();

    // eproj = eseq @ W_in[512:]
    mma_gemm_kernel<<<dim3(H_ / 128, (TD * B_) / 128), 256>>>(
        TD * B_, H_, E_, pEsH, pEsL, pWintH, pWintL, pEproj, nullptr, 0);

    // W_comb = W_o @ W_in[:512], then transpose
    sgemm_kernel<<<dim3(H_ / 128, H_ / 128), 256>>>(
        H_, H_, H_, Wo, H_, Win, H_, pWcomb, nullptr, 0);
    transpose512_kernel<<<dim3(16, 16), dim3(32, 8)>>>(pWcomb, pWcombT);

    // ==== the whole 64-step scan in ONE persistent kernel ====
    scan_kernel<<<NBLK, NTHR, SCAN_SMEM_FLOATS * 4>>>(
        Wq, vlen, Wih, Whh, bih, bhh, lng, lnb, alph);

    // logits = ys @ W_dense + b_dense (HMMA), transposed write to (B,T,V)
    mma_gemm_kernel<<<dim3(V_ / 128, (TD * B_) / 128), 256>>>(
        TD * B_, V_, H_, pYsH, pYsL, pWdtH, pWdtL, out, bd, 1);

    // final hidden state (t=63 odd -> final state lives in g_hA)
    if (out_size >= BTV + LBH)
        copy_kernel<<<(LBH + 255) / 256, 256>>>(pHA, out + BTV, LBH);
}